// round 1
// baseline (speedup 1.0000x reference)
#include <cuda_runtime.h>
#include <math.h>

// Problem constants
#define B   32
#define C   512
#define HW  196          // 14*14
#define D   8192
#define PAIRS (C*C)      // 262144

// ---------------- device scratch (no allocations allowed) ----------------
__device__ int   g_h[2][C];
__device__ float g_s[2][C];
__device__ float g_G[(size_t)B * C * C];        // [b][i][j]   32 MB
__device__ float g_Gt[(size_t)PAIRS * B];       // [i*512+j][b] 32 MB (b innermost)
__device__ float g_Yt[(size_t)D * B];           // [d][b]       1 MB
__device__ int   g_cnt[D];
__device__ int   g_off[D];
__device__ int   g_fill[D];
__device__ int   g_pairs[PAIRS];                // packed: bit31 = sign<0, low 18 bits = i*512+j

// ---------------- 1. extract (h, s) from dense sketch matrices ----------------
__global__ void extract_kernel(const float* __restrict__ S1,
                               const float* __restrict__ S2) {
    int w    = (blockIdx.x * blockDim.x + threadIdx.x) >> 5;   // 1024 warps
    int lane = threadIdx.x & 31;
    if (w >= 2 * C) return;
    int mat = w >> 9;
    int row = w & (C - 1);
    const float* r = (mat ? S2 : S1) + (size_t)row * D;
    int   idx = -1;
    float sg  = 0.f;
    for (int c = lane; c < D; c += 32) {
        float v = r[c];
        if (fabsf(v) > 0.5f) { idx = c; sg = v; }
    }
    unsigned m = __ballot_sync(0xffffffffu, idx >= 0);
    int src = m ? (__ffs(m) - 1) : 0;
    idx = __shfl_sync(0xffffffffu, idx, src);
    sg  = __shfl_sync(0xffffffffu, sg,  src);
    if (lane == 0) {
        g_h[mat][row] = (idx < 0) ? 0 : idx;
        g_s[mat][row] = (idx < 0) ? 0.f : sg;
    }
}

// ---------------- 2. CSR build over the 262144 (i,j) -> bin pairs ----------------
__global__ void zero_cnt_kernel() {
    g_cnt[blockIdx.x * 1024 + threadIdx.x] = 0;
}

__global__ void pair_count_kernel() {
    int t = blockIdx.x * blockDim.x + threadIdx.x;     // 0..262143
    int i = t >> 9, j = t & 511;
    int d = (g_h[0][i] + g_h[1][j]) & (D - 1);
    atomicAdd(&g_cnt[d], 1);
}

__global__ void scan_kernel() {                         // 1 block, 1024 threads, 8 bins each
    __shared__ int sh[1024];
    int t = threadIdx.x;
    int base = t * 8;
    int loc[8];
    int s = 0;
    #pragma unroll
    for (int l = 0; l < 8; l++) { loc[l] = s; s += g_cnt[base + l]; }
    sh[t] = s;
    __syncthreads();
    for (int off = 1; off < 1024; off <<= 1) {
        int v = (t >= off) ? sh[t - off] : 0;
        __syncthreads();
        sh[t] += v;
        __syncthreads();
    }
    int excl = (t == 0) ? 0 : sh[t - 1];
    #pragma unroll
    for (int l = 0; l < 8; l++) {
        g_off[base + l]  = excl + loc[l];
        g_fill[base + l] = 0;
    }
}

__global__ void pair_fill_kernel() {
    int t = blockIdx.x * blockDim.x + threadIdx.x;
    int i = t >> 9, j = t & 511;
    int d = (g_h[0][i] + g_h[1][j]) & (D - 1);
    int slot = g_off[d] + atomicAdd(&g_fill[d], 1);
    float sg = g_s[0][i] * g_s[1][j];
    g_pairs[slot] = t | ((sg < 0.f) ? 0x80000000 : 0);
}

// ---------------- 3. batched Gram  G[b] = X_b X_b^T  (symmetric tiles) ----------------
#define BM 64
#define BK 16
#define BPAD 68

__global__ __launch_bounds__(256) void gram_kernel(const float* __restrict__ x) {
    int b = blockIdx.y;
    // decode upper-triangular tile pair (ti <= tj) from blockIdx.x in [0,36)
    int ti = 0, rem = blockIdx.x;
    while (rem >= 8 - ti) { rem -= 8 - ti; ti++; }
    int tj = ti + rem;

    __shared__ float As[BK][BPAD];
    __shared__ float Bs[BK][BPAD];

    const float* Xb = x + (size_t)b * C * HW;
    int tx = threadIdx.x & 15;      // n dir
    int ty = threadIdx.x >> 4;      // m dir
    int mload = threadIdx.x >> 2;          // 0..63
    int kload = (threadIdx.x & 3) * 4;     // 0,4,8,12

    float acc[4][4] = {};

    for (int k0 = 0; k0 < HW; k0 += BK) {
        #pragma unroll
        for (int l = 0; l < 4; l++) {
            int k = k0 + kload + l;
            float a = 0.f, bb = 0.f;
            if (k < HW) {
                a  = Xb[(size_t)(ti * BM + mload) * HW + k];
                bb = Xb[(size_t)(tj * BM + mload) * HW + k];
            }
            As[kload + l][mload] = a;
            Bs[kload + l][mload] = bb;
        }
        __syncthreads();
        #pragma unroll
        for (int k = 0; k < BK; k++) {
            float4 a4 = *(const float4*)&As[k][ty * 4];
            float4 b4 = *(const float4*)&Bs[k][tx * 4];
            float av[4] = {a4.x, a4.y, a4.z, a4.w};
            float bv[4] = {b4.x, b4.y, b4.z, b4.w};
            #pragma unroll
            for (int mi = 0; mi < 4; mi++)
                #pragma unroll
                for (int ni = 0; ni < 4; ni++)
                    acc[mi][ni] += av[mi] * bv[ni];
        }
        __syncthreads();
    }

    float* Gb = g_G + (size_t)b * C * C;
    #pragma unroll
    for (int mi = 0; mi < 4; mi++) {
        int gm = ti * BM + ty * 4 + mi;
        #pragma unroll
        for (int ni = 0; ni < 4; ni++) {
            int gn = tj * BM + tx * 4 + ni;
            float v = acc[mi][ni];
            Gb[(size_t)gm * C + gn] = v;
            if (ti != tj) Gb[(size_t)gn * C + gm] = v;
        }
    }
}

// ---------------- 4. transpose G[b][ij] -> G_t[ij][b] ----------------
__global__ void transpose_kernel() {                    // 8192 blocks x 256 thr, 32x32 tiles
    __shared__ float tile[32][33];
    int ij0 = blockIdx.x * 32;
    int tid = threadIdx.x;
    #pragma unroll
    for (int p = 0; p < 4; p++) {
        int e = tid + p * 256;
        int bb = e >> 5, c = e & 31;
        tile[bb][c] = g_G[(size_t)bb * PAIRS + ij0 + c];
    }
    __syncthreads();
    #pragma unroll
    for (int p = 0; p < 4; p++) {
        int e = tid + p * 256;
        int r = e >> 5, c = e & 31;
        g_Gt[(size_t)(ij0 + r) * B + c] = tile[c][r];
    }
}

// ---------------- 5. atomic-free gather: warp per bin, lane = batch ----------------
__global__ void gather_kernel() {                       // 1024 blocks x 256 thr = 8192 warps
    int g    = (blockIdx.x * blockDim.x + threadIdx.x) >> 5;
    int lane = threadIdx.x & 31;
    if (g >= D) return;
    int beg = g_off[g];
    int cnt = g_cnt[g];
    float acc = 0.f;
    for (int p = 0; p < cnt; p++) {
        int e  = g_pairs[beg + p];
        int ij = e & 0x3FFFF;
        float v = g_Gt[(size_t)ij * B + lane];
        acc = (e < 0) ? (acc - v) : (acc + v);
    }
    g_Yt[(size_t)g * B + lane] = acc;
}

// ---------------- 6. signed sqrt + L2 normalize ----------------
__global__ void finalize_kernel(float* __restrict__ out) {   // 32 blocks x 256 thr
    __shared__ float ysh[D];     // 32 KB
    __shared__ float red[8];
    int b = blockIdx.x;
    int t = threadIdx.x;
    float ss = 0.f;
    for (int d = t; d < D; d += 256) {
        float y  = g_Yt[(size_t)d * B + b];
        float sg = (y > 0.f) ? 1.f : ((y < 0.f) ? -1.f : 0.f);
        float v  = sg * sqrtf(fabsf(y) + 1e-8f);
        ysh[d] = v;
        ss += v * v;
    }
    #pragma unroll
    for (int o = 16; o; o >>= 1) ss += __shfl_xor_sync(0xffffffffu, ss, o);
    if ((t & 31) == 0) red[t >> 5] = ss;
    __syncthreads();
    if (t < 32) {
        float v2 = (t < 8) ? red[t] : 0.f;
        #pragma unroll
        for (int o = 4; o; o >>= 1) v2 += __shfl_xor_sync(0xffffffffu, v2, o);
        if (t == 0) red[0] = v2;
    }
    __syncthreads();
    float inv = 1.f / fmaxf(sqrtf(red[0]), 1e-12f);
    for (int d = t; d < D; d += 256)
        out[(size_t)b * D + d] = ysh[d] * inv;
}

// ---------------- launcher ----------------
extern "C" void kernel_launch(void* const* d_in, const int* in_sizes, int n_in,
                              void* d_out, int out_size) {
    // Identify x by size (1,605,632 elems); the two 4,194,304-elem tensors are S1, S2 in order.
    const float* x  = nullptr;
    const float* S1 = nullptr;
    const float* S2 = nullptr;
    for (int i = 0; i < n_in; i++) {
        if (in_sizes[i] == B * C * HW) { x = (const float*)d_in[i]; }
        else if (!S1)                  { S1 = (const float*)d_in[i]; }
        else                           { S2 = (const float*)d_in[i]; }
    }
    float* out = (float*)d_out;

    extract_kernel   <<<128, 256>>>(S1, S2);
    zero_cnt_kernel  <<<8, 1024>>>();
    pair_count_kernel<<<PAIRS / 512, 512>>>();
    scan_kernel      <<<1, 1024>>>();
    pair_fill_kernel <<<PAIRS / 512, 512>>>();
    gram_kernel      <<<dim3(36, B), 256>>>(x);
    transpose_kernel <<<PAIRS / 32, 256>>>();
    gather_kernel    <<<D / 8, 256>>>();
    finalize_kernel  <<<B, 256>>>(out);
}

// round 2
// speedup vs baseline: 1.0770x; 1.0770x over previous
#include <cuda_runtime.h>
#include <cuda_bf16.h>
#include <mma.h>
#include <math.h>

using namespace nvcuda;

// Problem constants
#define B   32
#define C   512
#define HW  196          // 14*14
#define D   8192
#define PAIRS (C*C)      // 262144
#define KP  208          // HW padded to 13*16
#define NCH 39           // 3 segments * 13 chunks of 16
#define LDT 24           // smem leading dim (bf16 elems), multiple of 8

// ---------------- device scratch (no allocations allowed) ----------------
__device__ int   g_h[2][C];
__device__ float g_s[2][C];
__device__ __align__(32) __nv_bfloat16 g_Ah[(size_t)B * C * KP];  // hi part, 6.8 MB
__device__ __align__(32) __nv_bfloat16 g_Al[(size_t)B * C * KP];  // lo part, 6.8 MB
__device__ float g_G[(size_t)B * C * C];        // [b][i][j]   32 MB
__device__ float g_Gt[(size_t)PAIRS * B];       // [i*512+j][b] 32 MB (b innermost)
__device__ float g_Yt[(size_t)D * B];           // [d][b]       1 MB
__device__ int   g_cnt[D];
__device__ int   g_off[D];
__device__ int   g_fill[D];
__device__ int   g_pairs[PAIRS];                // packed: bit31 = sign<0, low 18 bits = i*512+j

// ---------------- 0. bf16 split-pack of x ----------------
__global__ void prep_kernel(const float* __restrict__ x) {
    int bc = blockIdx.x;            // 0 .. B*C-1
    int k  = threadIdx.x;           // 256 threads, guard to KP
    if (k >= KP) return;
    float v = (k < HW) ? x[(size_t)bc * HW + k] : 0.f;
    __nv_bfloat16 hi = __float2bfloat16(v);
    float lo = v - __bfloat162float(hi);
    g_Ah[(size_t)bc * KP + k] = hi;
    g_Al[(size_t)bc * KP + k] = __float2bfloat16(lo);
}

// ---------------- 1. extract (h, s) from dense sketch matrices (+ zero cnt) ----------------
__global__ void extract_kernel(const float* __restrict__ S1,
                               const float* __restrict__ S2) {
    int gt = blockIdx.x * blockDim.x + threadIdx.x;
    if (gt < D) g_cnt[gt] = 0;                     // fold in histogram zeroing
    int w    = gt >> 5;                            // 1024 warps
    int lane = threadIdx.x & 31;
    if (w >= 2 * C) return;
    int mat = w >> 9;
    int row = w & (C - 1);
    const float* r = (mat ? S2 : S1) + (size_t)row * D;
    int   idx = -1;
    float sg  = 0.f;
    for (int c = lane; c < D; c += 32) {
        float v = r[c];
        if (fabsf(v) > 0.5f) { idx = c; sg = v; }
    }
    unsigned m = __ballot_sync(0xffffffffu, idx >= 0);
    int src = m ? (__ffs(m) - 1) : 0;
    idx = __shfl_sync(0xffffffffu, idx, src);
    sg  = __shfl_sync(0xffffffffu, sg,  src);
    if (lane == 0) {
        g_h[mat][row] = (idx < 0) ? 0 : idx;
        g_s[mat][row] = (idx < 0) ? 0.f : sg;
    }
}

// ---------------- 2. CSR build over the 262144 (i,j) -> bin pairs ----------------
__global__ void pair_count_kernel() {
    int t = blockIdx.x * blockDim.x + threadIdx.x;     // 0..262143
    int i = t >> 9, j = t & 511;
    int d = (g_h[0][i] + g_h[1][j]) & (D - 1);
    atomicAdd(&g_cnt[d], 1);
}

__global__ void scan_kernel() {        // 1 block, 256 threads, 32 bins each
    __shared__ int wsum[8];
    __shared__ int woff[8];
    int t = threadIdx.x;
    int base = t * 32;
    int s = 0;
    #pragma unroll
    for (int l = 0; l < 32; l++) s += g_cnt[base + l];
    int lane = t & 31, w = t >> 5;
    int v = s;
    #pragma unroll
    for (int o = 1; o < 32; o <<= 1) {
        int u = __shfl_up_sync(0xffffffffu, v, o);
        if (lane >= o) v += u;
    }
    if (lane == 31) wsum[w] = v;
    __syncthreads();
    if (t == 0) {
        int r = 0;
        #pragma unroll
        for (int i = 0; i < 8; i++) { woff[i] = r; r += wsum[i]; }
    }
    __syncthreads();
    int run = v - s + woff[w];     // exclusive prefix for this thread's first bin
    #pragma unroll
    for (int l = 0; l < 32; l++) {
        int c = g_cnt[base + l];
        g_off[base + l]  = run;
        g_fill[base + l] = 0;
        run += c;
    }
}

__global__ void pair_fill_kernel() {
    int t = blockIdx.x * blockDim.x + threadIdx.x;
    int i = t >> 9, j = t & 511;
    int d = (g_h[0][i] + g_h[1][j]) & (D - 1);
    int slot = g_off[d] + atomicAdd(&g_fill[d], 1);
    float sg = g_s[0][i] * g_s[1][j];
    g_pairs[slot] = t | ((sg < 0.f) ? 0x80000000 : 0);
}

// ---------------- 3. batched Gram via bf16-split wmma ----------------
//   G = A.B^T, A segments over K: [hi, hi, lo], B segments: [hi, lo, hi]
//   => G = Xh.Xh^T + Xh.Xl^T + Xl.Xh^T   (drops Xl.Xl^T, ~2^-16 relative)
__global__ __launch_bounds__(256) void gram_mma(const float* __restrict__ unused) {
    int b = blockIdx.y;
    int ti = 0, rem = blockIdx.x;                // upper-triangular tile pair, ti <= tj
    while (rem >= 8 - ti) { rem -= 8 - ti; ti++; }
    int tj = ti + rem;

    __shared__ __align__(32) __nv_bfloat16 As[64 * LDT];
    __shared__ __align__(32) __nv_bfloat16 Bs[64 * LDT];

    int tid  = threadIdx.x;
    int warp = tid >> 5;
    int wr   = warp >> 1;        // 0..3  (m)
    int wc   = warp & 1;         // 0..1  (n, 32 wide)

    wmma::fragment<wmma::accumulator, 16, 16, 16, float> acc0, acc1;
    wmma::fill_fragment(acc0, 0.f);
    wmma::fill_fragment(acc1, 0.f);

    const __nv_bfloat16* baseHi = g_Ah + (size_t)b * C * KP;
    const __nv_bfloat16* baseLo = g_Al + (size_t)b * C * KP;

    int lr = tid >> 2;           // 0..63 row
    int lc = (tid & 3) * 4;      // 0,4,8,12 col (4 bf16 = 8B)

    for (int kc = 0; kc < NCH; kc++) {
        int seg = (kc < 13) ? 0 : (kc < 26) ? 1 : 2;
        int ko  = (kc - seg * 13) * 16;
        const __nv_bfloat16* Pa = (seg == 2) ? baseLo : baseHi;   // hi,hi,lo
        const __nv_bfloat16* Pb = (seg == 1) ? baseLo : baseHi;   // hi,lo,hi

        *(uint2*)&As[lr * LDT + lc] =
            *(const uint2*)&Pa[(size_t)(ti * 64 + lr) * KP + ko + lc];
        *(uint2*)&Bs[lr * LDT + lc] =
            *(const uint2*)&Pb[(size_t)(tj * 64 + lr) * KP + ko + lc];
        __syncthreads();

        wmma::fragment<wmma::matrix_a, 16, 16, 16, __nv_bfloat16, wmma::row_major> af;
        wmma::fragment<wmma::matrix_b, 16, 16, 16, __nv_bfloat16, wmma::col_major> bf0, bf1;
        wmma::load_matrix_sync(af,  &As[(wr * 16) * LDT], LDT);
        wmma::load_matrix_sync(bf0, &Bs[(wc * 32) * LDT], LDT);
        wmma::load_matrix_sync(bf1, &Bs[(wc * 32 + 16) * LDT], LDT);
        wmma::mma_sync(acc0, af, bf0, acc0);
        wmma::mma_sync(acc1, af, bf1, acc1);
        __syncthreads();
    }

    float* Gb = g_G + (size_t)b * C * C;
    int gm = ti * 64 + wr * 16;
    int gn = tj * 64 + wc * 32;
    wmma::store_matrix_sync(&Gb[(size_t)gm * C + gn],      acc0, C, wmma::mem_row_major);
    wmma::store_matrix_sync(&Gb[(size_t)gm * C + gn + 16], acc1, C, wmma::mem_row_major);
    if (ti != tj) {
        wmma::store_matrix_sync(&Gb[(size_t)gn * C + gm],        acc0, C, wmma::mem_col_major);
        wmma::store_matrix_sync(&Gb[(size_t)(gn + 16) * C + gm], acc1, C, wmma::mem_col_major);
    }
}

// ---------------- 4. transpose G[b][ij] -> G_t[ij][b] ----------------
__global__ void transpose_kernel() {                    // 8192 blocks x 256 thr, 32x32 tiles
    __shared__ float tile[32][33];
    int ij0 = blockIdx.x * 32;
    int tid = threadIdx.x;
    #pragma unroll
    for (int p = 0; p < 4; p++) {
        int e = tid + p * 256;
        int bb = e >> 5, c = e & 31;
        tile[bb][c] = g_G[(size_t)bb * PAIRS + ij0 + c];
    }
    __syncthreads();
    #pragma unroll
    for (int p = 0; p < 4; p++) {
        int e = tid + p * 256;
        int r = e >> 5, c = e & 31;
        g_Gt[(size_t)(ij0 + r) * B + c] = tile[c][r];
    }
}

// ---------------- 5. atomic-free gather: warp per bin, lane = batch ----------------
__global__ void gather_kernel() {                       // 1024 blocks x 256 thr = 8192 warps
    int g    = (blockIdx.x * blockDim.x + threadIdx.x) >> 5;
    int lane = threadIdx.x & 31;
    if (g >= D) return;
    int beg = g_off[g];
    int cnt = g_cnt[g];
    float acc = 0.f;
    for (int p = 0; p < cnt; p++) {
        int e  = g_pairs[beg + p];
        int ij = e & 0x3FFFF;
        float v = g_Gt[(size_t)ij * B + lane];
        acc = (e < 0) ? (acc - v) : (acc + v);
    }
    g_Yt[(size_t)g * B + lane] = acc;
}

// ---------------- 6. signed sqrt + L2 normalize ----------------
__global__ void finalize_kernel(float* __restrict__ out) {   // 32 blocks x 256 thr
    __shared__ float ysh[D];     // 32 KB
    __shared__ float red[8];
    int b = blockIdx.x;
    int t = threadIdx.x;
    float ss = 0.f;
    for (int d = t; d < D; d += 256) {
        float y  = g_Yt[(size_t)d * B + b];
        float sg = (y > 0.f) ? 1.f : ((y < 0.f) ? -1.f : 0.f);
        float v  = sg * sqrtf(fabsf(y) + 1e-8f);
        ysh[d] = v;
        ss += v * v;
    }
    #pragma unroll
    for (int o = 16; o; o >>= 1) ss += __shfl_xor_sync(0xffffffffu, ss, o);
    if ((t & 31) == 0) red[t >> 5] = ss;
    __syncthreads();
    if (t < 32) {
        float v2 = (t < 8) ? red[t] : 0.f;
        #pragma unroll
        for (int o = 4; o; o >>= 1) v2 += __shfl_xor_sync(0xffffffffu, v2, o);
        if (t == 0) red[0] = v2;
    }
    __syncthreads();
    float inv = 1.f / fmaxf(sqrtf(red[0]), 1e-12f);
    for (int d = t; d < D; d += 256)
        out[(size_t)b * D + d] = ysh[d] * inv;
}

// ---------------- launcher ----------------
extern "C" void kernel_launch(void* const* d_in, const int* in_sizes, int n_in,
                              void* d_out, int out_size) {
    const float* x  = nullptr;
    const float* S1 = nullptr;
    const float* S2 = nullptr;
    for (int i = 0; i < n_in; i++) {
        if (in_sizes[i] == B * C * HW) { x = (const float*)d_in[i]; }
        else if (!S1)                  { S1 = (const float*)d_in[i]; }
        else                           { S2 = (const float*)d_in[i]; }
    }
    float* out = (float*)d_out;

    prep_kernel      <<<B * C, 256>>>(x);
    extract_kernel   <<<128, 256>>>(S1, S2);
    pair_count_kernel<<<PAIRS / 512, 512>>>();
    scan_kernel      <<<1, 256>>>();
    pair_fill_kernel <<<PAIRS / 512, 512>>>();
    gram_mma         <<<dim3(36, B), 256>>>(x);
    transpose_kernel <<<PAIRS / 32, 256>>>();
    gather_kernel    <<<D / 8, 256>>>();
    finalize_kernel  <<<B, 256>>>(out);
}

// round 3
// speedup vs baseline: 1.1474x; 1.0654x over previous
#include <cuda_runtime.h>
#include <cuda_bf16.h>
#include <mma.h>
#include <math.h>

using namespace nvcuda;

// Problem constants
#define B   32
#define C   512
#define HW  196          // 14*14
#define D   8192
#define PAIRS (C*C)      // 262144
#define KP  208          // HW padded to 13*16
#define LDK 216          // smem row stride in bf16 (208 + 8 pad), 432B (16B-mult)

// ---------------- device scratch (no allocations allowed) ----------------
__device__ int   g_h[2][C];
__device__ float g_s[2][C];
__device__ __align__(32) __nv_bfloat16 g_Ah[(size_t)B * C * KP];  // hi part
__device__ __align__(32) __nv_bfloat16 g_Al[(size_t)B * C * KP];  // lo part
__device__ float g_G[(size_t)B * C * C];        // [b][i][j]
__device__ float g_Gt[(size_t)PAIRS * B];       // [i*512+j][b] (b innermost)
__device__ float g_Yt[(size_t)D * B];           // [d][b]
__device__ int   g_cnt[D];
__device__ int   g_off[D];
__device__ int   g_fill[D];
__device__ int   g_pairs[PAIRS];                // bit31 = sign<0, low 18 bits = i*512+j

// ---------------- 1. fused: bf16 split-pack of x  +  sketch extraction ----------------
__global__ void setup_kernel(const float* __restrict__ x,
                             const float* __restrict__ S1,
                             const float* __restrict__ S2) {
    if (blockIdx.x < B * C) {
        // ---- prep: split x row into bf16 hi/lo ----
        int bc = blockIdx.x;
        int k  = threadIdx.x;
        if (k >= KP) return;
        float v = (k < HW) ? x[(size_t)bc * HW + k] : 0.f;
        __nv_bfloat16 hi = __float2bfloat16(v);
        float lo = v - __bfloat162float(hi);
        g_Ah[(size_t)bc * KP + k] = hi;
        g_Al[(size_t)bc * KP + k] = __float2bfloat16(lo);
        return;
    }
    // ---- extract (h, s) from dense sketch matrices; also zero g_cnt ----
    int bx = blockIdx.x - B * C;                   // 0..127
    int gt = bx * blockDim.x + threadIdx.x;
    if (gt < D) g_cnt[gt] = 0;
    int w    = gt >> 5;                            // 1024 warps
    int lane = threadIdx.x & 31;
    if (w >= 2 * C) return;
    int mat = w >> 9;
    int row = w & (C - 1);
    const float4* r = (const float4*)((mat ? S2 : S1) + (size_t)row * D);
    int   idx = -1;
    float sg  = 0.f;
    for (int c = lane; c < D / 4; c += 32) {
        float4 v = r[c];
        if (fabsf(v.x) > 0.5f) { idx = 4 * c + 0; sg = v.x; }
        if (fabsf(v.y) > 0.5f) { idx = 4 * c + 1; sg = v.y; }
        if (fabsf(v.z) > 0.5f) { idx = 4 * c + 2; sg = v.z; }
        if (fabsf(v.w) > 0.5f) { idx = 4 * c + 3; sg = v.w; }
    }
    unsigned m = __ballot_sync(0xffffffffu, idx >= 0);
    int src = m ? (__ffs(m) - 1) : 0;
    idx = __shfl_sync(0xffffffffu, idx, src);
    sg  = __shfl_sync(0xffffffffu, sg,  src);
    if (lane == 0) {
        g_h[mat][row] = (idx < 0) ? 0 : idx;
        g_s[mat][row] = (idx < 0) ? 0.f : sg;
    }
}

// ---------------- 2. CSR build over the 262144 (i,j) -> bin pairs ----------------
__global__ void pair_count_kernel() {
    int t = blockIdx.x * blockDim.x + threadIdx.x;     // 0..262143
    int i = t >> 9, j = t & 511;
    int d = (g_h[0][i] + g_h[1][j]) & (D - 1);
    atomicAdd(&g_cnt[d], 1);
}

__global__ void scan_kernel() {        // 1 block, 256 threads; smem-staged coalesced
    __shared__ int sc[D];              // 32 KB
    __shared__ int wsum[8];
    __shared__ int woff[8];
    int t = threadIdx.x;
    const int4* c4 = (const int4*)g_cnt;
    int4* s4 = (int4*)sc;
    #pragma unroll
    for (int q = 0; q < 8; q++) s4[q * 256 + t] = c4[q * 256 + t];   // coalesced
    __syncthreads();
    int base = t * 32;
    int s = 0;
    #pragma unroll
    for (int l = 0; l < 32; l++) s += sc[base + l];
    int lane = t & 31, w = t >> 5;
    int v = s;
    #pragma unroll
    for (int o = 1; o < 32; o <<= 1) {
        int u = __shfl_up_sync(0xffffffffu, v, o);
        if (lane >= o) v += u;
    }
    if (lane == 31) wsum[w] = v;
    __syncthreads();
    if (t == 0) {
        int r = 0;
        #pragma unroll
        for (int i = 0; i < 8; i++) { woff[i] = r; r += wsum[i]; }
    }
    __syncthreads();
    int run = v - s + woff[w];
    #pragma unroll
    for (int l = 0; l < 32; l++) {
        int c = sc[base + l];
        g_off[base + l]  = run;
        g_fill[base + l] = 0;
        run += c;
    }
}

__global__ void pair_fill_kernel() {
    int t = blockIdx.x * blockDim.x + threadIdx.x;
    int i = t >> 9, j = t & 511;
    int d = (g_h[0][i] + g_h[1][j]) & (D - 1);
    int slot = g_off[d] + atomicAdd(&g_fill[d], 1);
    float sg = g_s[0][i] * g_s[1][j];
    g_pairs[slot] = t | ((sg < 0.f) ? 0x80000000 : 0);
}

// ---------------- 3. batched Gram via bf16-split wmma, single smem load ----------------
//   G = Xh.Xh^T + Xh.Xl^T + Xl.Xh^T   (drops Xl.Xl^T, ~2^-16 relative)
__global__ __launch_bounds__(256) void gram_mma() {
    int b = blockIdx.y;
    int ti = 0, rem = blockIdx.x;                // upper-triangular tile pair, ti <= tj
    while (rem >= 8 - ti) { rem -= 8 - ti; ti++; }
    int tj = ti + rem;

    extern __shared__ __align__(16) __nv_bfloat16 sm[];
    __nv_bfloat16* Ahi = sm;                     // 64 x LDK each
    __nv_bfloat16* Ali = sm + 1 * 64 * LDK;
    __nv_bfloat16* Bhj = sm + 2 * 64 * LDK;
    __nv_bfloat16* Blj = sm + 3 * 64 * LDK;

    int tid  = threadIdx.x;
    int warp = tid >> 5;
    int wr   = warp >> 1;        // 0..3  (m)
    int wc   = warp & 1;         // 0..1  (n, 32 wide)

    const __nv_bfloat16* gHi = g_Ah + (size_t)b * C * KP;
    const __nv_bfloat16* gLo = g_Al + (size_t)b * C * KP;

    // Load the four 64x208 tiles once (uint4 = 8 bf16; 26 per row)
    const __nv_bfloat16* srcs[4] = { gHi + (size_t)ti * 64 * KP,
                                     gLo + (size_t)ti * 64 * KP,
                                     gHi + (size_t)tj * 64 * KP,
                                     gLo + (size_t)tj * 64 * KP };
    __nv_bfloat16* dsts[4] = { Ahi, Ali, Bhj, Blj };
    #pragma unroll
    for (int tle = 0; tle < 4; tle++) {
        const __nv_bfloat16* src = srcs[tle];
        __nv_bfloat16* dst = dsts[tle];
        for (int idx = tid; idx < 64 * 26; idx += 256) {
            int row = idx / 26, q = idx - row * 26;
            *(uint4*)&dst[row * LDK + q * 8] = *(const uint4*)&src[row * KP + q * 8];
        }
    }
    __syncthreads();

    wmma::fragment<wmma::accumulator, 16, 16, 16, float> acc0, acc1;
    wmma::fill_fragment(acc0, 0.f);
    wmma::fill_fragment(acc1, 0.f);

    #pragma unroll 1
    for (int kc = 0; kc < 13; kc++) {
        int ko = kc * 16;
        wmma::fragment<wmma::matrix_a, 16, 16, 16, __nv_bfloat16, wmma::row_major> ah, al;
        wmma::fragment<wmma::matrix_b, 16, 16, 16, __nv_bfloat16, wmma::col_major> bh0, bh1, bl0, bl1;
        wmma::load_matrix_sync(ah,  &Ahi[(wr * 16) * LDK + ko], LDK);
        wmma::load_matrix_sync(al,  &Ali[(wr * 16) * LDK + ko], LDK);
        wmma::load_matrix_sync(bh0, &Bhj[(wc * 32) * LDK + ko], LDK);
        wmma::load_matrix_sync(bh1, &Bhj[(wc * 32 + 16) * LDK + ko], LDK);
        wmma::load_matrix_sync(bl0, &Blj[(wc * 32) * LDK + ko], LDK);
        wmma::load_matrix_sync(bl1, &Blj[(wc * 32 + 16) * LDK + ko], LDK);
        wmma::mma_sync(acc0, ah, bh0, acc0);     // hi*hi
        wmma::mma_sync(acc1, ah, bh1, acc1);
        wmma::mma_sync(acc0, ah, bl0, acc0);     // hi*lo
        wmma::mma_sync(acc1, ah, bl1, acc1);
        wmma::mma_sync(acc0, al, bh0, acc0);     // lo*hi
        wmma::mma_sync(acc1, al, bh1, acc1);
    }

    float* Gb = g_G + (size_t)b * C * C;
    int gm = ti * 64 + wr * 16;
    int gn = tj * 64 + wc * 32;
    wmma::store_matrix_sync(&Gb[(size_t)gm * C + gn],      acc0, C, wmma::mem_row_major);
    wmma::store_matrix_sync(&Gb[(size_t)gm * C + gn + 16], acc1, C, wmma::mem_row_major);
    if (ti != tj) {
        wmma::store_matrix_sync(&Gb[(size_t)gn * C + gm],        acc0, C, wmma::mem_col_major);
        wmma::store_matrix_sync(&Gb[(size_t)(gn + 16) * C + gm], acc1, C, wmma::mem_col_major);
    }
}

// ---------------- 4. transpose G[b][ij] -> G_t[ij][b] ----------------
__global__ void transpose_kernel() {                    // 8192 blocks x 256 thr, 32x32 tiles
    __shared__ float tile[32][33];
    int ij0 = blockIdx.x * 32;
    int tid = threadIdx.x;
    #pragma unroll
    for (int p = 0; p < 4; p++) {
        int e = tid + p * 256;
        int bb = e >> 5, c = e & 31;
        tile[bb][c] = g_G[(size_t)bb * PAIRS + ij0 + c];
    }
    __syncthreads();
    #pragma unroll
    for (int p = 0; p < 4; p++) {
        int e = tid + p * 256;
        int r = e >> 5, c = e & 31;
        g_Gt[(size_t)(ij0 + r) * B + c] = tile[c][r];
    }
}

// ---------------- 5. atomic-free gather: warp per bin, lane = batch ----------------
__global__ void gather_kernel() {                       // 8192 warps
    int g    = (blockIdx.x * blockDim.x + threadIdx.x) >> 5;
    int lane = threadIdx.x & 31;
    if (g >= D) return;
    int beg = g_off[g];
    int cnt = g_cnt[g];
    float acc = 0.f;
    for (int p = 0; p < cnt; p++) {
        int e  = g_pairs[beg + p];
        int ij = e & 0x3FFFF;
        float v = g_Gt[(size_t)ij * B + lane];
        acc = (e < 0) ? (acc - v) : (acc + v);
    }
    g_Yt[(size_t)g * B + lane] = acc;
}

// ---------------- 6. signed sqrt + L2 normalize ----------------
__global__ void finalize_kernel(float* __restrict__ out) {   // 32 blocks x 256 thr
    __shared__ float ysh[D];
    __shared__ float red[8];
    int b = blockIdx.x;
    int t = threadIdx.x;
    float ss = 0.f;
    for (int d = t; d < D; d += 256) {
        float y  = g_Yt[(size_t)d * B + b];
        float sg = (y > 0.f) ? 1.f : ((y < 0.f) ? -1.f : 0.f);
        float v  = sg * sqrtf(fabsf(y) + 1e-8f);
        ysh[d] = v;
        ss += v * v;
    }
    #pragma unroll
    for (int o = 16; o; o >>= 1) ss += __shfl_xor_sync(0xffffffffu, ss, o);
    if ((t & 31) == 0) red[t >> 5] = ss;
    __syncthreads();
    if (t < 32) {
        float v2 = (t < 8) ? red[t] : 0.f;
        #pragma unroll
        for (int o = 4; o; o >>= 1) v2 += __shfl_xor_sync(0xffffffffu, v2, o);
        if (t == 0) red[0] = v2;
    }
    __syncthreads();
    float inv = 1.f / fmaxf(sqrtf(red[0]), 1e-12f);
    for (int d = t; d < D; d += 256)
        out[(size_t)b * D + d] = ysh[d] * inv;
}

// ---------------- launcher ----------------
extern "C" void kernel_launch(void* const* d_in, const int* in_sizes, int n_in,
                              void* d_out, int out_size) {
    const float* x  = nullptr;
    const float* S1 = nullptr;
    const float* S2 = nullptr;
    for (int i = 0; i < n_in; i++) {
        if (in_sizes[i] == B * C * HW) { x = (const float*)d_in[i]; }
        else if (!S1)                  { S1 = (const float*)d_in[i]; }
        else                           { S2 = (const float*)d_in[i]; }
    }
    float* out = (float*)d_out;

    const int gram_smem = 4 * 64 * LDK * (int)sizeof(__nv_bfloat16);   // 110,592 B
    cudaFuncSetAttribute(gram_mma, cudaFuncAttributeMaxDynamicSharedMemorySize, gram_smem);

    setup_kernel     <<<B * C + 128, 256>>>(x, S1, S2);
    pair_count_kernel<<<PAIRS / 512, 512>>>();
    scan_kernel      <<<1, 256>>>();
    pair_fill_kernel <<<PAIRS / 512, 512>>>();
    gram_mma         <<<dim3(36, B), 256, gram_smem>>>();
    transpose_kernel <<<PAIRS / 32, 256>>>();
    gather_kernel    <<<D / 8, 256>>>();
    finalize_kernel  <<<B, 256>>>(out);
}

// round 4
// speedup vs baseline: 1.5425x; 1.3443x over previous
#include <cuda_runtime.h>
#include <cuda_bf16.h>
#include <mma.h>
#include <math.h>

using namespace nvcuda;

// Problem constants
#define B   32
#define C   512
#define HW  196          // 14*14
#define D   8192
#define KP  208          // HW padded to 13*16
#define LDK 216          // smem row stride in bf16 (208 + 8 pad)
#define BC  (B * C)      // 16384

// ---------------- device scratch (no allocations allowed) ----------------
__device__ int   g_h[2][C];
__device__ float g_s[2][C];
__device__ __align__(32) __nv_bfloat16 g_Ah[(size_t)B * C * KP];  // hi part
__device__ __align__(32) __nv_bfloat16 g_Al[(size_t)B * C * KP];  // lo part
__device__ float g_Yt[(size_t)B * D];           // [b][d], atomically accumulated

// ---------------- 1. fused: split-pack x, extract (h,s), zero Yt ----------------
__global__ void setup_kernel(const float* __restrict__ x,
                             const float* __restrict__ S1,
                             const float* __restrict__ S2) {
    int bx = blockIdx.x;
    int t  = threadIdx.x;
    if (bx < BC) {
        // ---- prep: split x row into bf16 hi/lo ----
        if (t >= KP) return;
        float v = (t < HW) ? x[(size_t)bx * HW + t] : 0.f;
        __nv_bfloat16 hi = __float2bfloat16(v);
        float lo = v - __bfloat162float(hi);
        g_Ah[(size_t)bx * KP + t] = hi;
        g_Al[(size_t)bx * KP + t] = __float2bfloat16(lo);
        return;
    }
    if (bx < BC + 1024) {
        // ---- extract: one block per sketch row; exactly one +-1 entry per row ----
        int row = bx - BC;
        int mat = row >> 9;
        int r   = row & (C - 1);
        const float4* p = (const float4*)((mat ? S2 : S1) + (size_t)r * D);
        int   idx = -1;
        float sg  = 0.f;
        #pragma unroll
        for (int q = 0; q < 8; q++) {
            int c = t + q * 256;                 // 2048 float4 per row
            float4 v = p[c];
            if (fabsf(v.x) > 0.5f) { idx = 4 * c + 0; sg = v.x; }
            if (fabsf(v.y) > 0.5f) { idx = 4 * c + 1; sg = v.y; }
            if (fabsf(v.z) > 0.5f) { idx = 4 * c + 2; sg = v.z; }
            if (fabsf(v.w) > 0.5f) { idx = 4 * c + 3; sg = v.w; }
        }
        if (idx >= 0) {                          // exactly one thread hits
            g_h[mat][r] = idx;
            g_s[mat][r] = sg;
        }
        return;
    }
    // ---- zero Yt: 256 blocks x 256 thr x float4 ----
    int zb = bx - BC - 1024;                     // 0..255
    float4* y4 = (float4*)g_Yt;
    y4[zb * 256 + t] = make_float4(0.f, 0.f, 0.f, 0.f);
}

// ---------------- 2. Gram (bf16-split wmma) with fused count-sketch scatter ----------------
//   G = Xh.Xh^T + Xh.Xl^T + Xl.Xh^T  (drops Xl.Xl^T, ~2^-16 relative)
//   Epilogue: Yt[b][ (h1[i]+h2[j]) & 8191 ] += s1[i]*s2[j] * G[b][i][j]
__global__ __launch_bounds__(256) void gram_scatter() {
    int b = blockIdx.y;
    int ti = 0, rem = blockIdx.x;                // upper-triangular tile pair, ti <= tj
    while (rem >= 8 - ti) { rem -= 8 - ti; ti++; }
    int tj = ti + rem;

    extern __shared__ __align__(16) __nv_bfloat16 sm[];
    __nv_bfloat16* Ahi = sm;                     // 64 x LDK each (110,592 B total)
    __nv_bfloat16* Ali = sm + 1 * 64 * LDK;
    __nv_bfloat16* Bhj = sm + 2 * 64 * LDK;
    __nv_bfloat16* Blj = sm + 3 * 64 * LDK;

    int tid  = threadIdx.x;
    int warp = tid >> 5;
    int wr   = warp >> 1;        // 0..3  (m)
    int wc   = warp & 1;         // 0..1  (n, 32 wide)

    const __nv_bfloat16* gHi = g_Ah + (size_t)b * C * KP;
    const __nv_bfloat16* gLo = g_Al + (size_t)b * C * KP;

    const __nv_bfloat16* srcs[4] = { gHi + (size_t)ti * 64 * KP,
                                     gLo + (size_t)ti * 64 * KP,
                                     gHi + (size_t)tj * 64 * KP,
                                     gLo + (size_t)tj * 64 * KP };
    __nv_bfloat16* dsts[4] = { Ahi, Ali, Bhj, Blj };
    #pragma unroll
    for (int tle = 0; tle < 4; tle++) {
        const __nv_bfloat16* src = srcs[tle];
        __nv_bfloat16* dst = dsts[tle];
        for (int idx = tid; idx < 64 * 26; idx += 256) {
            int row = idx / 26, q = idx - row * 26;
            *(uint4*)&dst[row * LDK + q * 8] = *(const uint4*)&src[row * KP + q * 8];
        }
    }
    __syncthreads();

    wmma::fragment<wmma::accumulator, 16, 16, 16, float> acc0, acc1;
    wmma::fill_fragment(acc0, 0.f);
    wmma::fill_fragment(acc1, 0.f);

    #pragma unroll 1
    for (int kc = 0; kc < 13; kc++) {
        int ko = kc * 16;
        wmma::fragment<wmma::matrix_a, 16, 16, 16, __nv_bfloat16, wmma::row_major> ah, al;
        wmma::fragment<wmma::matrix_b, 16, 16, 16, __nv_bfloat16, wmma::col_major> bh0, bh1, bl0, bl1;
        wmma::load_matrix_sync(ah,  &Ahi[(wr * 16) * LDK + ko], LDK);
        wmma::load_matrix_sync(al,  &Ali[(wr * 16) * LDK + ko], LDK);
        wmma::load_matrix_sync(bh0, &Bhj[(wc * 32) * LDK + ko], LDK);
        wmma::load_matrix_sync(bh1, &Bhj[(wc * 32 + 16) * LDK + ko], LDK);
        wmma::load_matrix_sync(bl0, &Blj[(wc * 32) * LDK + ko], LDK);
        wmma::load_matrix_sync(bl1, &Blj[(wc * 32 + 16) * LDK + ko], LDK);
        wmma::mma_sync(acc0, ah, bh0, acc0);     // hi*hi
        wmma::mma_sync(acc1, ah, bh1, acc1);
        wmma::mma_sync(acc0, ah, bl0, acc0);     // hi*lo
        wmma::mma_sync(acc1, ah, bl1, acc1);
        wmma::mma_sync(acc0, al, bh0, acc0);     // lo*hi
        wmma::mma_sync(acc1, al, bh1, acc1);
    }

    // ---- epilogue: stage tile + hash tables into (aliased) smem, then scatter ----
    __syncthreads();                             // smem loads done; safe to overwrite
    float* stage = (float*)sm;                   // 64 x 68 floats
    const int LDS2 = 68;
    int*   hh = (int*)(stage + 64 * LDS2);       // 4 x 64 ints
    float* ss = (float*)(hh + 256);              // 4 x 64 floats

    int gm = ti * 64, gn = tj * 64;
    if (tid < 64) {
        hh[tid]       = g_h[0][gm + tid];        // h1 over row range
        hh[64 + tid]  = g_h[1][gn + tid];        // h2 over col range
        hh[128 + tid] = g_h[0][gn + tid];        // h1 over col range (mirror)
        hh[192 + tid] = g_h[1][gm + tid];        // h2 over row range (mirror)
        ss[tid]       = g_s[0][gm + tid];
        ss[64 + tid]  = g_s[1][gn + tid];
        ss[128 + tid] = g_s[0][gn + tid];
        ss[192 + tid] = g_s[1][gm + tid];
    }
    wmma::store_matrix_sync(&stage[(wr * 16) * LDS2 + wc * 32],      acc0, LDS2, wmma::mem_row_major);
    wmma::store_matrix_sync(&stage[(wr * 16) * LDS2 + wc * 32 + 16], acc1, LDS2, wmma::mem_row_major);
    __syncthreads();

    float* Yb = g_Yt + (size_t)b * D;
    bool mirror = (ti != tj);
    #pragma unroll 4
    for (int e = tid; e < 4096; e += 256) {
        int r = e >> 6, c = e & 63;
        float v = stage[r * LDS2 + c];
        int   d1 = (hh[r] + hh[64 + c]) & (D - 1);
        float w1 = ss[r] * ss[64 + c];
        atomicAdd(&Yb[d1], v * w1);
        if (mirror) {
            int   d2 = (hh[128 + c] + hh[192 + r]) & (D - 1);
            float w2 = ss[128 + c] * ss[192 + r];
            atomicAdd(&Yb[d2], v * w2);
        }
    }
}

// ---------------- 3. signed sqrt + L2 normalize ----------------
__global__ void finalize_kernel(float* __restrict__ out) {   // 32 blocks x 256 thr
    __shared__ float ysh[D];
    __shared__ float red[8];
    int b = blockIdx.x;
    int t = threadIdx.x;
    float ssum = 0.f;
    for (int d = t; d < D; d += 256) {
        float y  = g_Yt[(size_t)b * D + d];
        float sg = (y > 0.f) ? 1.f : ((y < 0.f) ? -1.f : 0.f);
        float v  = sg * sqrtf(fabsf(y) + 1e-8f);
        ysh[d] = v;
        ssum += v * v;
    }
    #pragma unroll
    for (int o = 16; o; o >>= 1) ssum += __shfl_xor_sync(0xffffffffu, ssum, o);
    if ((t & 31) == 0) red[t >> 5] = ssum;
    __syncthreads();
    if (t < 32) {
        float v2 = (t < 8) ? red[t] : 0.f;
        #pragma unroll
        for (int o = 4; o; o >>= 1) v2 += __shfl_xor_sync(0xffffffffu, v2, o);
        if (t == 0) red[0] = v2;
    }
    __syncthreads();
    float inv = 1.f / fmaxf(sqrtf(red[0]), 1e-12f);
    for (int d = t; d < D; d += 256)
        out[(size_t)b * D + d] = ysh[d] * inv;
}

// ---------------- launcher ----------------
extern "C" void kernel_launch(void* const* d_in, const int* in_sizes, int n_in,
                              void* d_out, int out_size) {
    const float* x  = nullptr;
    const float* S1 = nullptr;
    const float* S2 = nullptr;
    for (int i = 0; i < n_in; i++) {
        if (in_sizes[i] == B * C * HW) { x = (const float*)d_in[i]; }
        else if (!S1)                  { S1 = (const float*)d_in[i]; }
        else                           { S2 = (const float*)d_in[i]; }
    }
    float* out = (float*)d_out;

    const int gram_smem = 4 * 64 * LDK * (int)sizeof(__nv_bfloat16);   // 110,592 B
    static int smem_set = 0;
    if (!smem_set) {
        cudaFuncSetAttribute(gram_scatter, cudaFuncAttributeMaxDynamicSharedMemorySize, gram_smem);
        smem_set = 1;
    }

    setup_kernel  <<<BC + 1024 + 256, 256>>>(x, S1, S2);
    gram_scatter  <<<dim3(36, B), 256, gram_smem>>>();
    finalize_kernel<<<B, 256>>>(out);
}

// round 6
// speedup vs baseline: 1.7766x; 1.1518x over previous
#include <cuda_runtime.h>
#include <cuda_bf16.h>
#include <mma.h>
#include <math.h>

using namespace nvcuda;

// Problem constants
#define B   32
#define C   512
#define HW  196          // 14*14
#define D   8192
#define KP  208          // HW padded to 13*16
#define LDK 216          // smem row stride in bf16 (208 + 8 pad)
#define BC  (B * C)      // 16384

// ---------------- device scratch (no allocations allowed) ----------------
__device__ int   g_h[2][C];
__device__ float g_s[2][C];
__device__ __align__(32) __nv_bfloat16 g_Ah[(size_t)BC * KP];  // hi part
__device__ __align__(32) __nv_bfloat16 g_Al[(size_t)BC * KP];  // lo part
__device__ float g_Yt[(size_t)B * D];           // [b][d], atomically accumulated

// ---------------- 1. fused: split-pack x, extract (h,s), zero Yt ----------------
__global__ void setup_kernel(const float* __restrict__ x,
                             const float* __restrict__ S1,
                             const float* __restrict__ S2) {
    int bx = blockIdx.x;
    int t  = threadIdx.x;
    if (bx < 1024) {
        // ---- prep: 16 x-rows per block, split into bf16 hi/lo ----
        int base = bx * 16;
        for (int e = t; e < 16 * KP; e += 256) {
            int r = e / KP, k = e - r * KP;
            int bc = base + r;
            float v = (k < HW) ? x[(size_t)bc * HW + k] : 0.f;
            __nv_bfloat16 hi = __float2bfloat16(v);
            float lo = v - __bfloat162float(hi);
            g_Ah[(size_t)bc * KP + k] = hi;
            g_Al[(size_t)bc * KP + k] = __float2bfloat16(lo);
        }
        return;
    }
    if (bx < 1024 + 4096) {
        // ---- extract: 4 blocks per sketch row (quarter rows); one +-1 per row ----
        int q    = bx - 1024;
        int row  = q >> 2;
        int part = q & 3;
        int mat = row >> 9;
        int r   = row & (C - 1);
        const float4* p = (const float4*)((mat ? S2 : S1) + (size_t)r * D) + part * 512;
        float4 v0 = p[t];
        float4 v1 = p[t + 256];
        int   idx = -1;
        float sg  = 0.f;
        int c0 = part * 2048 + 4 * t;
        if (fabsf(v0.x) > 0.5f) { idx = c0 + 0; sg = v0.x; }
        if (fabsf(v0.y) > 0.5f) { idx = c0 + 1; sg = v0.y; }
        if (fabsf(v0.z) > 0.5f) { idx = c0 + 2; sg = v0.z; }
        if (fabsf(v0.w) > 0.5f) { idx = c0 + 3; sg = v0.w; }
        int c1 = c0 + 1024;
        if (fabsf(v1.x) > 0.5f) { idx = c1 + 0; sg = v1.x; }
        if (fabsf(v1.y) > 0.5f) { idx = c1 + 1; sg = v1.y; }
        if (fabsf(v1.z) > 0.5f) { idx = c1 + 2; sg = v1.z; }
        if (fabsf(v1.w) > 0.5f) { idx = c1 + 3; sg = v1.w; }
        if (idx >= 0) {                          // exactly one thread (whole grid) hits per row
            g_h[mat][r] = idx;
            g_s[mat][r] = sg;
        }
        return;
    }
    // ---- zero Yt: 256 blocks x 256 thr x float4 ----
    int zb = bx - 1024 - 4096;
    float4* y4 = (float4*)g_Yt;
    y4[zb * 256 + t] = make_float4(0.f, 0.f, 0.f, 0.f);
}

// ---------------- 2. Gram (bf16-split wmma) with fused count-sketch scatter ----------------
//   G = Xh.Xh^T + Xh.Xl^T + Xl.Xh^T  (drops Xl.Xl^T, ~2^-16 relative)
//   128 threads / 4 warps, each warp computes a 32x32 region of the 64x64 tile.
__global__ __launch_bounds__(128, 2) void gram_scatter() {
    int b = blockIdx.y;
    int ti = 0, rem = blockIdx.x;                // upper-triangular tile pair, ti <= tj
    while (rem >= 8 - ti) { rem -= 8 - ti; ti++; }
    int tj = ti + rem;

    extern __shared__ __align__(16) __nv_bfloat16 sm[];
    __nv_bfloat16* Ahi = sm;                     // 64 x LDK each (110,592 B total)
    __nv_bfloat16* Ali = sm + 1 * 64 * LDK;
    __nv_bfloat16* Bhj = sm + 2 * 64 * LDK;
    __nv_bfloat16* Blj = sm + 3 * 64 * LDK;

    int tid  = threadIdx.x;
    int warp = tid >> 5;
    int wr   = warp >> 1;        // 0..1 (m, 32 rows)
    int wc   = warp & 1;         // 0..1 (n, 32 cols)

    const __nv_bfloat16* gHi = g_Ah + (size_t)b * C * KP;
    const __nv_bfloat16* gLo = g_Al + (size_t)b * C * KP;

    const __nv_bfloat16* srcs[4] = { gHi + (size_t)ti * 64 * KP,
                                     gLo + (size_t)ti * 64 * KP,
                                     gHi + (size_t)tj * 64 * KP,
                                     gLo + (size_t)tj * 64 * KP };
    __nv_bfloat16* dsts[4] = { Ahi, Ali, Bhj, Blj };
    #pragma unroll
    for (int tle = 0; tle < 4; tle++) {
        const __nv_bfloat16* src = srcs[tle];
        __nv_bfloat16* dst = dsts[tle];
        #pragma unroll 4
        for (int idx = tid; idx < 64 * 26; idx += 128) {
            int row = idx / 26, q = idx - row * 26;
            *(uint4*)&dst[row * LDK + q * 8] = *(const uint4*)&src[row * KP + q * 8];
        }
    }
    __syncthreads();

    wmma::fragment<wmma::accumulator, 16, 16, 16, float> acc[2][2];
    #pragma unroll
    for (int mi = 0; mi < 2; mi++)
        #pragma unroll
        for (int ni = 0; ni < 2; ni++)
            wmma::fill_fragment(acc[mi][ni], 0.f);

    #pragma unroll
    for (int kc = 0; kc < 13; kc++) {
        int ko = kc * 16;
        wmma::fragment<wmma::matrix_a, 16, 16, 16, __nv_bfloat16, wmma::row_major> ah[2], al[2];
        wmma::fragment<wmma::matrix_b, 16, 16, 16, __nv_bfloat16, wmma::col_major> bh[2], bl[2];
        #pragma unroll
        for (int mi = 0; mi < 2; mi++) {
            wmma::load_matrix_sync(ah[mi], &Ahi[(wr * 32 + mi * 16) * LDK + ko], LDK);
            wmma::load_matrix_sync(al[mi], &Ali[(wr * 32 + mi * 16) * LDK + ko], LDK);
        }
        #pragma unroll
        for (int ni = 0; ni < 2; ni++) {
            wmma::load_matrix_sync(bh[ni], &Bhj[(wc * 32 + ni * 16) * LDK + ko], LDK);
            wmma::load_matrix_sync(bl[ni], &Blj[(wc * 32 + ni * 16) * LDK + ko], LDK);
        }
        #pragma unroll
        for (int mi = 0; mi < 2; mi++)
            #pragma unroll
            for (int ni = 0; ni < 2; ni++) {
                wmma::mma_sync(acc[mi][ni], ah[mi], bh[ni], acc[mi][ni]);  // hi*hi
                wmma::mma_sync(acc[mi][ni], ah[mi], bl[ni], acc[mi][ni]);  // hi*lo
                wmma::mma_sync(acc[mi][ni], al[mi], bh[ni], acc[mi][ni]);  // lo*hi
            }
    }

    // ---- epilogue: stage tile + hash tables into (aliased) smem, then scatter ----
    __syncthreads();                             // smem reads done; safe to overwrite
    float* stage = (float*)sm;                   // 64 x 68 floats
    const int LDS2 = 68;
    int*   hh = (int*)(stage + 64 * LDS2);       // 4 x 64 ints
    float* ss = (float*)(hh + 256);              // 4 x 64 floats

    int gm = ti * 64, gn = tj * 64;
    if (tid < 64) {
        hh[tid]       = g_h[0][gm + tid];        // h1 over row range
        hh[64 + tid]  = g_h[1][gn + tid];        // h2 over col range
        hh[128 + tid] = g_h[0][gn + tid];        // h1 over col range (mirror)
        hh[192 + tid] = g_h[1][gm + tid];        // h2 over row range (mirror)
        ss[tid]       = g_s[0][gm + tid];
        ss[64 + tid]  = g_s[1][gn + tid];
        ss[128 + tid] = g_s[0][gn + tid];
        ss[192 + tid] = g_s[1][gm + tid];
    }
    #pragma unroll
    for (int mi = 0; mi < 2; mi++)
        #pragma unroll
        for (int ni = 0; ni < 2; ni++)
            wmma::store_matrix_sync(&stage[(wr * 32 + mi * 16) * LDS2 + wc * 32 + ni * 16],
                                    acc[mi][ni], LDS2, wmma::mem_row_major);
    __syncthreads();

    float* Yb = g_Yt + (size_t)b * D;
    bool mirror = (ti != tj);
    #pragma unroll 4
    for (int e = tid; e < 4096; e += 128) {
        int r = e >> 6, c = e & 63;
        float v = stage[r * LDS2 + c];
        int   d1 = (hh[r] + hh[64 + c]) & (D - 1);
        float w1 = ss[r] * ss[64 + c];
        atomicAdd(&Yb[d1], v * w1);
        if (mirror) {
            int   d2 = (hh[128 + c] + hh[192 + r]) & (D - 1);
            float w2 = ss[128 + c] * ss[192 + r];
            atomicAdd(&Yb[d2], v * w2);
        }
    }
}

// ---------------- 3. signed sqrt + L2 normalize ----------------
__global__ void finalize_kernel(float* __restrict__ out) {   // 32 blocks x 256 thr
    __shared__ float ysh[D];
    __shared__ float red[8];
    int b = blockIdx.x;
    int t = threadIdx.x;
    float ssum = 0.f;
    for (int d = t; d < D; d += 256) {
        float y  = g_Yt[(size_t)b * D + d];
        float sg = (y > 0.f) ? 1.f : ((y < 0.f) ? -1.f : 0.f);
        float v  = sg * sqrtf(fabsf(y) + 1e-8f);
        ysh[d] = v;
        ssum += v * v;
    }
    #pragma unroll
    for (int o = 16; o; o >>= 1) ssum += __shfl_xor_sync(0xffffffffu, ssum, o);
    if ((t & 31) == 0) red[t >> 5] = ssum;
    __syncthreads();
    if (t < 32) {
        float v2 = (t < 8) ? red[t] : 0.f;
        #pragma unroll
        for (int o = 4; o; o >>= 1) v2 += __shfl_xor_sync(0xffffffffu, v2, o);
        if (t == 0) red[0] = v2;
    }
    __syncthreads();
    float inv = 1.f / fmaxf(sqrtf(red[0]), 1e-12f);
    for (int d = t; d < D; d += 256)
        out[(size_t)b * D + d] = ysh[d] * inv;
}

// ---------------- launcher ----------------
extern "C" void kernel_launch(void* const* d_in, const int* in_sizes, int n_in,
                              void* d_out, int out_size) {
    const float* x  = nullptr;
    const float* S1 = nullptr;
    const float* S2 = nullptr;
    for (int i = 0; i < n_in; i++) {
        if (in_sizes[i] == B * C * HW) { x = (const float*)d_in[i]; }
        else if (!S1)                  { S1 = (const float*)d_in[i]; }
        else                           { S2 = (const float*)d_in[i]; }
    }
    float* out = (float*)d_out;

    const int gram_smem = 4 * 64 * LDK * (int)sizeof(__nv_bfloat16);   // 110,592 B
    static int smem_set = 0;
    if (!smem_set) {
        cudaFuncSetAttribute(gram_scatter, cudaFuncAttributeMaxDynamicSharedMemorySize, gram_smem);
        smem_set = 1;
    }

    setup_kernel   <<<1024 + 4096 + 256, 256>>>(x, S1, S2);
    gram_scatter   <<<dim3(36, B), 128, gram_smem>>>();
    finalize_kernel<<<B, 256>>>(out);
}

// round 7
// speedup vs baseline: 2.4494x; 1.3787x over previous
#include <cuda_runtime.h>
#include <cuda_bf16.h>
#include <mma.h>
#include <math.h>

using namespace nvcuda;

// Problem constants
#define B   32
#define C   512
#define HW  196          // 14*14
#define D   8192
#define KP  208          // HW padded to 13*16
#define LDK 216          // smem row stride in bf16 (208 + 8 pad)
#define BC  (B * C)      // 16384
#define LDS2 68          // stage row stride (floats)
#define STAGE_F (64 * LDS2)              // floats per batch stage
#define SMEM_DYN (4*64*LDK*2 + 4*STAGE_F*4)   // 110592 + 69632 = 180224

// ---------------- device scratch (no allocations allowed) ----------------
__device__ int   g_h[2][C];
__device__ float g_s[2][C];
__device__ __align__(32) __nv_bfloat16 g_Ah[(size_t)BC * KP];  // hi part
__device__ __align__(32) __nv_bfloat16 g_Al[(size_t)BC * KP];  // lo part
__device__ float g_Yt[(size_t)D * B];           // [d][b]  (b innermost!)

// ---------------- 1. fused: split-pack x, extract (h,s), zero Yt ----------------
__global__ void setup_kernel(const float* __restrict__ x,
                             const float* __restrict__ S1,
                             const float* __restrict__ S2) {
    int bx = blockIdx.x;
    int t  = threadIdx.x;
    if (bx < 1024) {
        // ---- prep: 16 x-rows per block, split into bf16 hi/lo ----
        int base = bx * 16;
        for (int e = t; e < 16 * KP; e += 256) {
            int r = e / KP, k = e - r * KP;
            int bc = base + r;
            float v = (k < HW) ? x[(size_t)bc * HW + k] : 0.f;
            __nv_bfloat16 hi = __float2bfloat16(v);
            float lo = v - __bfloat162float(hi);
            g_Ah[(size_t)bc * KP + k] = hi;
            g_Al[(size_t)bc * KP + k] = __float2bfloat16(lo);
        }
        return;
    }
    if (bx < 1024 + 4096) {
        // ---- extract: 4 blocks per sketch row (quarter rows); one +-1 per row ----
        int q    = bx - 1024;
        int row  = q >> 2;
        int part = q & 3;
        int mat = row >> 9;
        int r   = row & (C - 1);
        const float4* p = (const float4*)((mat ? S2 : S1) + (size_t)r * D) + part * 512;
        float4 v0 = p[t];
        float4 v1 = p[t + 256];
        int   idx = -1;
        float sg  = 0.f;
        int c0 = part * 2048 + 4 * t;
        if (fabsf(v0.x) > 0.5f) { idx = c0 + 0; sg = v0.x; }
        if (fabsf(v0.y) > 0.5f) { idx = c0 + 1; sg = v0.y; }
        if (fabsf(v0.z) > 0.5f) { idx = c0 + 2; sg = v0.z; }
        if (fabsf(v0.w) > 0.5f) { idx = c0 + 3; sg = v0.w; }
        int c1 = c0 + 1024;
        if (fabsf(v1.x) > 0.5f) { idx = c1 + 0; sg = v1.x; }
        if (fabsf(v1.y) > 0.5f) { idx = c1 + 1; sg = v1.y; }
        if (fabsf(v1.z) > 0.5f) { idx = c1 + 2; sg = v1.z; }
        if (fabsf(v1.w) > 0.5f) { idx = c1 + 3; sg = v1.w; }
        if (idx >= 0) {                          // exactly one thread (whole grid) hits per row
            g_h[mat][r] = idx;
            g_s[mat][r] = sg;
        }
        return;
    }
    // ---- zero Yt: 256 blocks x 256 thr x float4 ----
    int zb = bx - 1024 - 4096;
    float4* y4 = (float4*)g_Yt;
    y4[zb * 256 + t] = make_float4(0.f, 0.f, 0.f, 0.f);
}

// ---------------- 2. Gram (bf16-split wmma), 4-batch groups, v4 red scatter ----------------
//   G = Xh.Xh^T + Xh.Xl^T + Xl.Xh^T  (drops Xl.Xl^T, ~2^-16 relative)
//   Yt[(h1[i]+h2[j])&8191][b] += s1[i]*s2[j]*G[b][i][j], 4 batches per red.v4
__global__ __launch_bounds__(256, 1) void gram_scatter() {
    int bg = blockIdx.y;                         // batch group: b = bg*4 + bi
    int ti = 0, rem = blockIdx.x;                // upper-triangular tile pair, ti <= tj
    while (rem >= 8 - ti) { rem -= 8 - ti; ti++; }
    int tj = ti + rem;
    bool diag = (ti == tj);

    extern __shared__ __align__(16) __nv_bfloat16 sm[];
    __nv_bfloat16* Ahi = sm;                     // 64 x LDK each
    __nv_bfloat16* Ali = sm + 1 * 64 * LDK;
    __nv_bfloat16* Bhj = sm + 2 * 64 * LDK;
    __nv_bfloat16* Blj = sm + 3 * 64 * LDK;
    float* stage = (float*)(sm + 4 * 64 * LDK);  // 4 x (64 x LDS2) floats
    __shared__ int   hh[256];
    __shared__ float ss[256];

    int tid  = threadIdx.x;
    int warp = tid >> 5;
    int wr   = warp >> 1;        // 0..3 (m, 16 rows)
    int wc   = warp & 1;         // 0..1 (n, 32 cols)

    int gm = ti * 64, gn = tj * 64;
    if (tid < 64) {
        hh[tid]       = g_h[0][gm + tid];        // h1 over row range
        hh[64 + tid]  = g_h[1][gn + tid];        // h2 over col range
        hh[128 + tid] = g_h[0][gn + tid];        // h1 over col range (mirror)
        hh[192 + tid] = g_h[1][gm + tid];        // h2 over row range (mirror)
        ss[tid]       = g_s[0][gm + tid];
        ss[64 + tid]  = g_s[1][gn + tid];
        ss[128 + tid] = g_s[0][gn + tid];
        ss[192 + tid] = g_s[1][gm + tid];
    }

    #pragma unroll 1
    for (int bi = 0; bi < 4; bi++) {
        int b = bg * 4 + bi;
        __syncthreads();                         // prev iter's tile reads done (and hh/ss ready)
        // ---- stage tiles for this batch ----
        const __nv_bfloat16* gHi = g_Ah + (size_t)b * C * KP;
        const __nv_bfloat16* gLo = g_Al + (size_t)b * C * KP;
        {
            const __nv_bfloat16* sa_h = gHi + (size_t)ti * 64 * KP;
            const __nv_bfloat16* sa_l = gLo + (size_t)ti * 64 * KP;
            const __nv_bfloat16* sb_h = gHi + (size_t)tj * 64 * KP;
            const __nv_bfloat16* sb_l = gLo + (size_t)tj * 64 * KP;
            #pragma unroll 2
            for (int idx = tid; idx < 64 * 26; idx += 256) {
                int row = idx / 26, q = idx - row * 26;
                int so = row * KP + q * 8, dof = row * LDK + q * 8;
                *(uint4*)&Ahi[dof] = *(const uint4*)&sa_h[so];
                *(uint4*)&Ali[dof] = *(const uint4*)&sa_l[so];
                if (!diag) {
                    *(uint4*)&Bhj[dof] = *(const uint4*)&sb_h[so];
                    *(uint4*)&Blj[dof] = *(const uint4*)&sb_l[so];
                }
            }
        }
        __syncthreads();

        const __nv_bfloat16* Ph = diag ? Ahi : Bhj;
        const __nv_bfloat16* Pl = diag ? Ali : Blj;

        wmma::fragment<wmma::accumulator, 16, 16, 16, float> acc0, acc1;
        wmma::fill_fragment(acc0, 0.f);
        wmma::fill_fragment(acc1, 0.f);

        #pragma unroll
        for (int kc = 0; kc < 13; kc++) {
            int ko = kc * 16;
            wmma::fragment<wmma::matrix_a, 16, 16, 16, __nv_bfloat16, wmma::row_major> ah, al;
            wmma::fragment<wmma::matrix_b, 16, 16, 16, __nv_bfloat16, wmma::col_major> bh0, bh1, bl0, bl1;
            wmma::load_matrix_sync(ah,  &Ahi[(wr * 16) * LDK + ko], LDK);
            wmma::load_matrix_sync(al,  &Ali[(wr * 16) * LDK + ko], LDK);
            wmma::load_matrix_sync(bh0, &Ph[(wc * 32) * LDK + ko], LDK);
            wmma::load_matrix_sync(bh1, &Ph[(wc * 32 + 16) * LDK + ko], LDK);
            wmma::load_matrix_sync(bl0, &Pl[(wc * 32) * LDK + ko], LDK);
            wmma::load_matrix_sync(bl1, &Pl[(wc * 32 + 16) * LDK + ko], LDK);
            wmma::mma_sync(acc0, ah, bh0, acc0);     // hi*hi
            wmma::mma_sync(acc1, ah, bh1, acc1);
            wmma::mma_sync(acc0, ah, bl0, acc0);     // hi*lo
            wmma::mma_sync(acc1, ah, bl1, acc1);
            wmma::mma_sync(acc0, al, bh0, acc0);     // lo*hi
            wmma::mma_sync(acc1, al, bh1, acc1);
        }

        float* st = stage + bi * STAGE_F;
        wmma::store_matrix_sync(&st[(wr * 16) * LDS2 + wc * 32],      acc0, LDS2, wmma::mem_row_major);
        wmma::store_matrix_sync(&st[(wr * 16) * LDS2 + wc * 32 + 16], acc1, LDS2, wmma::mem_row_major);
    }
    __syncthreads();

    // ---- scatter: one red.v4 per (pair, orientation) covering 4 batches ----
    float* Ybase = g_Yt + bg * 4;
    #pragma unroll 2
    for (int e = tid; e < 4096; e += 256) {
        int r = e >> 6, c = e & 63;
        int off = r * LDS2 + c;
        float v0 = stage[0 * STAGE_F + off];
        float v1 = stage[1 * STAGE_F + off];
        float v2 = stage[2 * STAGE_F + off];
        float v3 = stage[3 * STAGE_F + off];
        int   d1 = (hh[r] + hh[64 + c]) & (D - 1);
        float w1 = ss[r] * ss[64 + c];
        float* p1 = Ybase + (size_t)d1 * B;
        asm volatile("red.global.add.v4.f32 [%0], {%1, %2, %3, %4};"
                     :: "l"(p1), "f"(v0 * w1), "f"(v1 * w1), "f"(v2 * w1), "f"(v3 * w1)
                     : "memory");
        if (!diag) {
            int   d2 = (hh[128 + c] + hh[192 + r]) & (D - 1);
            float w2 = ss[128 + c] * ss[192 + r];
            float* p2 = Ybase + (size_t)d2 * B;
            asm volatile("red.global.add.v4.f32 [%0], {%1, %2, %3, %4};"
                         :: "l"(p2), "f"(v0 * w2), "f"(v1 * w2), "f"(v2 * w2), "f"(v3 * w2)
                         : "memory");
        }
    }
}

// ---------------- 3. signed sqrt + L2 normalize ----------------
__global__ void finalize_kernel(float* __restrict__ out) {   // 32 blocks x 256 thr
    __shared__ float ysh[D];
    __shared__ float red[8];
    int b = blockIdx.x;
    int t = threadIdx.x;
    float ssum = 0.f;
    for (int d = t; d < D; d += 256) {
        float y  = g_Yt[(size_t)d * B + b];
        float sg = (y > 0.f) ? 1.f : ((y < 0.f) ? -1.f : 0.f);
        float v  = sg * sqrtf(fabsf(y) + 1e-8f);
        ysh[d] = v;
        ssum += v * v;
    }
    #pragma unroll
    for (int o = 16; o; o >>= 1) ssum += __shfl_xor_sync(0xffffffffu, ssum, o);
    if ((t & 31) == 0) red[t >> 5] = ssum;
    __syncthreads();
    if (t < 32) {
        float v2 = (t < 8) ? red[t] : 0.f;
        #pragma unroll
        for (int o = 4; o; o >>= 1) v2 += __shfl_xor_sync(0xffffffffu, v2, o);
        if (t == 0) red[0] = v2;
    }
    __syncthreads();
    float inv = 1.f / fmaxf(sqrtf(red[0]), 1e-12f);
    for (int d = t; d < D; d += 256)
        out[(size_t)b * D + d] = ysh[d] * inv;
}

// ---------------- launcher ----------------
extern "C" void kernel_launch(void* const* d_in, const int* in_sizes, int n_in,
                              void* d_out, int out_size) {
    const float* x  = nullptr;
    const float* S1 = nullptr;
    const float* S2 = nullptr;
    for (int i = 0; i < n_in; i++) {
        if (in_sizes[i] == B * C * HW) { x = (const float*)d_in[i]; }
        else if (!S1)                  { S1 = (const float*)d_in[i]; }
        else                           { S2 = (const float*)d_in[i]; }
    }
    float* out = (float*)d_out;

    static int smem_set = 0;
    if (!smem_set) {
        cudaFuncSetAttribute(gram_scatter, cudaFuncAttributeMaxDynamicSharedMemorySize, SMEM_DYN);
        smem_set = 1;
    }

    setup_kernel   <<<1024 + 4096 + 256, 256>>>(x, S1, S2);
    gram_scatter   <<<dim3(36, 8), 256, SMEM_DYN>>>();
    finalize_kernel<<<B, 256>>>(out);
}

// round 8
// speedup vs baseline: 2.4598x; 1.0042x over previous
#include <cuda_runtime.h>
#include <cuda_bf16.h>
#include <mma.h>
#include <math.h>

using namespace nvcuda;

// Problem constants
#define B   32
#define C   512
#define HW  196          // 14*14
#define D   8192
#define KP  208          // HW padded to 13*16
#define LDK 216          // smem row stride in bf16 (208 + 8 pad)
#define BC  (B * C)      // 16384
#define LDS2 68          // stage row stride (floats)
#define STAGE_F (64 * LDS2)              // floats per batch stage
#define SMEM_DYN (4*64*LDK*2 + 4*STAGE_F*4)   // 110592 + 69632 = 180224

// ---------------- device scratch (no allocations allowed) ----------------
__device__ int   g_h[2][C];
__device__ float g_s[2][C];
__device__ __align__(32) __nv_bfloat16 g_Ah[(size_t)BC * KP];  // hi part
__device__ __align__(32) __nv_bfloat16 g_Al[(size_t)BC * KP];  // lo part
__device__ float g_Yt[(size_t)D * B];           // [d][b]  (b innermost)

// ---------------- 1. fused: split-pack x, extract (h,s), zero Yt ----------------
__global__ void setup_kernel(const float* __restrict__ x,
                             const float* __restrict__ S1,
                             const float* __restrict__ S2) {
    int bx = blockIdx.x;
    int t  = threadIdx.x;
    if (bx < 1024) {
        // ---- prep: 16 x-rows per block, split into bf16 hi/lo ----
        int base = bx * 16;
        for (int e = t; e < 16 * KP; e += 256) {
            int r = e / KP, k = e - r * KP;
            int bc = base + r;
            float v = (k < HW) ? x[(size_t)bc * HW + k] : 0.f;
            __nv_bfloat16 hi = __float2bfloat16(v);
            float lo = v - __bfloat162float(hi);
            g_Ah[(size_t)bc * KP + k] = hi;
            g_Al[(size_t)bc * KP + k] = __float2bfloat16(lo);
        }
        return;
    }
    if (bx < 1024 + 2048) {
        // ---- extract: 2 blocks per sketch row; 4 independent loads (MLP=4) ----
        int q    = bx - 1024;
        int row  = q >> 1;
        int half = q & 1;
        int mat = row >> 9;
        int r   = row & (C - 1);
        const float4* p = (const float4*)((mat ? S2 : S1) + (size_t)r * D) + half * 1024;
        float4 v[4];
        #pragma unroll
        for (int u = 0; u < 4; u++) v[u] = p[t + u * 256];
        int   idx = -1;
        float sg  = 0.f;
        #pragma unroll
        for (int u = 0; u < 4; u++) {
            int c = half * 4096 + 4 * (t + u * 256);
            if (fabsf(v[u].x) > 0.5f) { idx = c + 0; sg = v[u].x; }
            if (fabsf(v[u].y) > 0.5f) { idx = c + 1; sg = v[u].y; }
            if (fabsf(v[u].z) > 0.5f) { idx = c + 2; sg = v[u].z; }
            if (fabsf(v[u].w) > 0.5f) { idx = c + 3; sg = v[u].w; }
        }
        if (idx >= 0) {                          // exactly one thread (whole grid) hits per row
            g_h[mat][r] = idx;
            g_s[mat][r] = sg;
        }
        return;
    }
    // ---- zero Yt: 256 blocks x 256 thr x float4 ----
    int zb = bx - 1024 - 2048;
    float4* y4 = (float4*)g_Yt;
    y4[zb * 256 + t] = make_float4(0.f, 0.f, 0.f, 0.f);
}

// ---------------- 2. Gram (bf16-split wmma), 4-batch groups, v4 red scatter ----------------
//   G = Xh.Xh^T + Xh.Xl^T + Xl.Xh^T  (drops Xl.Xl^T, ~2^-16 relative)
//   Three independent accumulators per output tile (one per product) for HMMA ILP.
__global__ __launch_bounds__(256, 1) void gram_scatter() {
    int bg = blockIdx.y;                         // batch group: b = bg*4 + bi
    int ti = 0, rem = blockIdx.x;                // upper-triangular tile pair, ti <= tj
    while (rem >= 8 - ti) { rem -= 8 - ti; ti++; }
    int tj = ti + rem;
    bool diag = (ti == tj);

    extern __shared__ __align__(16) __nv_bfloat16 sm[];
    __nv_bfloat16* Ahi = sm;                     // 64 x LDK each
    __nv_bfloat16* Ali = sm + 1 * 64 * LDK;
    __nv_bfloat16* Bhj = sm + 2 * 64 * LDK;
    __nv_bfloat16* Blj = sm + 3 * 64 * LDK;
    float* stage = (float*)(sm + 4 * 64 * LDK);  // 4 x (64 x LDS2) floats
    __shared__ int   hh[256];
    __shared__ float ss[256];

    int tid  = threadIdx.x;
    int warp = tid >> 5;
    int wr   = warp >> 1;        // 0..3 (m, 16 rows)
    int wc   = warp & 1;         // 0..1 (n, 32 cols)

    int gm = ti * 64, gn = tj * 64;
    if (tid < 64) {
        hh[tid]       = g_h[0][gm + tid];        // h1 over row range
        hh[64 + tid]  = g_h[1][gn + tid];        // h2 over col range
        hh[128 + tid] = g_h[0][gn + tid];        // h1 over col range (mirror)
        hh[192 + tid] = g_h[1][gm + tid];        // h2 over row range (mirror)
        ss[tid]       = g_s[0][gm + tid];
        ss[64 + tid]  = g_s[1][gn + tid];
        ss[128 + tid] = g_s[0][gn + tid];
        ss[192 + tid] = g_s[1][gm + tid];
    }

    #pragma unroll 1
    for (int bi = 0; bi < 4; bi++) {
        int b = bg * 4 + bi;
        __syncthreads();                         // prev iter's tile reads done (and hh/ss ready)
        // ---- stage tiles for this batch ----
        const __nv_bfloat16* gHi = g_Ah + (size_t)b * C * KP;
        const __nv_bfloat16* gLo = g_Al + (size_t)b * C * KP;
        {
            const __nv_bfloat16* sa_h = gHi + (size_t)ti * 64 * KP;
            const __nv_bfloat16* sa_l = gLo + (size_t)ti * 64 * KP;
            const __nv_bfloat16* sb_h = gHi + (size_t)tj * 64 * KP;
            const __nv_bfloat16* sb_l = gLo + (size_t)tj * 64 * KP;
            #pragma unroll 2
            for (int idx = tid; idx < 64 * 26; idx += 256) {
                int row = idx / 26, q = idx - row * 26;
                int so = row * KP + q * 8, dof = row * LDK + q * 8;
                *(uint4*)&Ahi[dof] = *(const uint4*)&sa_h[so];
                *(uint4*)&Ali[dof] = *(const uint4*)&sa_l[so];
                if (!diag) {
                    *(uint4*)&Bhj[dof] = *(const uint4*)&sb_h[so];
                    *(uint4*)&Blj[dof] = *(const uint4*)&sb_l[so];
                }
            }
        }
        __syncthreads();

        const __nv_bfloat16* Ph = diag ? Ahi : Bhj;
        const __nv_bfloat16* Pl = diag ? Ali : Blj;

        // 2 output tiles x 3 independent product chains
        wmma::fragment<wmma::accumulator, 16, 16, 16, float> a0hh, a0hl, a0lh, a1hh, a1hl, a1lh;
        wmma::fill_fragment(a0hh, 0.f); wmma::fill_fragment(a0hl, 0.f); wmma::fill_fragment(a0lh, 0.f);
        wmma::fill_fragment(a1hh, 0.f); wmma::fill_fragment(a1hl, 0.f); wmma::fill_fragment(a1lh, 0.f);

        #pragma unroll
        for (int kc = 0; kc < 13; kc++) {
            int ko = kc * 16;
            wmma::fragment<wmma::matrix_a, 16, 16, 16, __nv_bfloat16, wmma::row_major> ah, al;
            wmma::fragment<wmma::matrix_b, 16, 16, 16, __nv_bfloat16, wmma::col_major> bh0, bh1, bl0, bl1;
            wmma::load_matrix_sync(ah,  &Ahi[(wr * 16) * LDK + ko], LDK);
            wmma::load_matrix_sync(al,  &Ali[(wr * 16) * LDK + ko], LDK);
            wmma::load_matrix_sync(bh0, &Ph[(wc * 32) * LDK + ko], LDK);
            wmma::load_matrix_sync(bh1, &Ph[(wc * 32 + 16) * LDK + ko], LDK);
            wmma::load_matrix_sync(bl0, &Pl[(wc * 32) * LDK + ko], LDK);
            wmma::load_matrix_sync(bl1, &Pl[(wc * 32 + 16) * LDK + ko], LDK);
            wmma::mma_sync(a0hh, ah, bh0, a0hh);     // all 6 independent
            wmma::mma_sync(a1hh, ah, bh1, a1hh);
            wmma::mma_sync(a0hl, ah, bl0, a0hl);
            wmma::mma_sync(a1hl, ah, bl1, a1hl);
            wmma::mma_sync(a0lh, al, bh0, a0lh);
            wmma::mma_sync(a1lh, al, bh1, a1lh);
        }
        #pragma unroll
        for (int e = 0; e < a0hh.num_elements; e++) {
            a0hh.x[e] += a0hl.x[e] + a0lh.x[e];
            a1hh.x[e] += a1hl.x[e] + a1lh.x[e];
        }

        float* st = stage + bi * STAGE_F;
        wmma::store_matrix_sync(&st[(wr * 16) * LDS2 + wc * 32],      a0hh, LDS2, wmma::mem_row_major);
        wmma::store_matrix_sync(&st[(wr * 16) * LDS2 + wc * 32 + 16], a1hh, LDS2, wmma::mem_row_major);
    }
    __syncthreads();

    // ---- scatter: one red.v4 per (pair, orientation) covering 4 batches ----
    float* Ybase = g_Yt + bg * 4;
    #pragma unroll 2
    for (int e = tid; e < 4096; e += 256) {
        int r = e >> 6, c = e & 63;
        int off = r * LDS2 + c;
        float v0 = stage[0 * STAGE_F + off];
        float v1 = stage[1 * STAGE_F + off];
        float v2 = stage[2 * STAGE_F + off];
        float v3 = stage[3 * STAGE_F + off];
        int   d1 = (hh[r] + hh[64 + c]) & (D - 1);
        float w1 = ss[r] * ss[64 + c];
        float* p1 = Ybase + (size_t)d1 * B;
        asm volatile("red.global.add.v4.f32 [%0], {%1, %2, %3, %4};"
                     :: "l"(p1), "f"(v0 * w1), "f"(v1 * w1), "f"(v2 * w1), "f"(v3 * w1)
                     : "memory");
        if (!diag) {
            int   d2 = (hh[128 + c] + hh[192 + r]) & (D - 1);
            float w2 = ss[128 + c] * ss[192 + r];
            float* p2 = Ybase + (size_t)d2 * B;
            asm volatile("red.global.add.v4.f32 [%0], {%1, %2, %3, %4};"
                         :: "l"(p2), "f"(v0 * w2), "f"(v1 * w2), "f"(v2 * w2), "f"(v3 * w2)
                         : "memory");
        }
    }
}

// ---------------- 3. signed sqrt + L2 normalize ----------------
__global__ void finalize_kernel(float* __restrict__ out) {   // 32 blocks x 256 thr
    __shared__ float ysh[D];
    __shared__ float red[8];
    int b = blockIdx.x;
    int t = threadIdx.x;
    float ssum = 0.f;
    for (int d = t; d < D; d += 256) {
        float y  = g_Yt[(size_t)d * B + b];
        float sg = (y > 0.f) ? 1.f : ((y < 0.f) ? -1.f : 0.f);
        float v  = sg * sqrtf(fabsf(y) + 1e-8f);
        ysh[d] = v;
        ssum += v * v;
    }
    #pragma unroll
    for (int o = 16; o; o >>= 1) ssum += __shfl_xor_sync(0xffffffffu, ssum, o);
    if ((t & 31) == 0) red[t >> 5] = ssum;
    __syncthreads();
    if (t < 32) {
        float v2 = (t < 8) ? red[t] : 0.f;
        #pragma unroll
        for (int o = 4; o; o >>= 1) v2 += __shfl_xor_sync(0xffffffffu, v2, o);
        if (t == 0) red[0] = v2;
    }
    __syncthreads();
    float inv = 1.f / fmaxf(sqrtf(red[0]), 1e-12f);
    for (int d = t; d < D; d += 256)
        out[(size_t)b * D + d] = ysh[d] * inv;
}

// ---------------- launcher ----------------
extern "C" void kernel_launch(void* const* d_in, const int* in_sizes, int n_in,
                              void* d_out, int out_size) {
    const float* x  = nullptr;
    const float* S1 = nullptr;
    const float* S2 = nullptr;
    for (int i = 0; i < n_in; i++) {
        if (in_sizes[i] == B * C * HW) { x = (const float*)d_in[i]; }
        else if (!S1)                  { S1 = (const float*)d_in[i]; }
        else                           { S2 = (const float*)d_in[i]; }
    }
    float* out = (float*)d_out;

    static int smem_set = 0;
    if (!smem_set) {
        cudaFuncSetAttribute(gram_scatter, cudaFuncAttributeMaxDynamicSharedMemorySize, SMEM_DYN);
        smem_set = 1;
    }

    setup_kernel   <<<1024 + 2048 + 256, 256>>>(x, S1, S2);
    gram_scatter   <<<dim3(36, 8), 256, SMEM_DYN>>>();
    finalize_kernel<<<B, 256>>>(out);
}